// round 3
// baseline (speedup 1.0000x reference)
#include <cuda_runtime.h>
#include <cuda_bf16.h>
#include <math.h>

// ---------------------------------------------------------------------------
// GAT 3-layer forward on GB300.
//   feat = H_in @ W  + fused el/er epilogue     (SGEMM, fp32)
//   edge kernel (per CSR position): ew = exp(lrelu(el[src]+er[dst])),
//        atomicAdd per-(dst,head) sums          (no max pass: shift-invariant)
//   agg kernel: out[dst] = (1/s) * sum ew * feat[src] + b   (warp-per-node-half)
// ---------------------------------------------------------------------------

#define MAXN 50000
#define MAXE 800000

__device__ float g_feat[MAXN * 256];
__device__ float g_bufA[MAXN * 256];
__device__ float g_bufB[MAXN * 256];
__device__ float g_el[MAXN * 4];
__device__ float g_er[MAXN * 4];
__device__ float g_ssum[MAXN * 4];
__device__ float g_ew[MAXE * 4];      // per-edge, per-head exp values (CSR order)
__device__ int   g_rowptr[MAXN + 1];
__device__ int   g_cursor[MAXN];
__device__ int   g_cnt[MAXN];
__device__ int   g_colsrc[MAXE];
__device__ int   g_coldst[MAXE];

// ---------------------------------------------------------------------------
// CSR build
// ---------------------------------------------------------------------------
__global__ void hist_kernel(const int* __restrict__ dst, int* __restrict__ cnt, int E) {
    int i = blockIdx.x * blockDim.x + threadIdx.x;
    if (i < E) atomicAdd(&cnt[dst[i]], 1);
}

__global__ void scan_kernel(const int* __restrict__ cnt, int* __restrict__ rowptr,
                            int* __restrict__ cursor, int N, int E) {
    __shared__ int sums[1024];
    int tid = threadIdx.x;
    int chunk = (N + 1023) >> 10;
    int start = tid * chunk;
    int end = min(start + chunk, N);
    int s = 0;
    for (int i = start; i < end; i++) s += cnt[i];
    sums[tid] = s;
    __syncthreads();
    for (int off = 1; off < 1024; off <<= 1) {
        int v = (tid >= off) ? sums[tid - off] : 0;
        __syncthreads();
        sums[tid] += v;
        __syncthreads();
    }
    int run = sums[tid] - s;  // exclusive prefix
    for (int i = start; i < end; i++) {
        rowptr[i] = run;
        cursor[i] = run;
        run += cnt[i];
    }
    if (tid == 0) rowptr[N] = E;
}

__global__ void scatter_kernel(const int* __restrict__ src, const int* __restrict__ dst,
                               int* __restrict__ cursor, int* __restrict__ colsrc,
                               int* __restrict__ coldst, int E) {
    int i = blockIdx.x * blockDim.x + threadIdx.x;
    if (i < E) {
        int d = dst[i];
        int p = atomicAdd(&cursor[d], 1);
        colsrc[p] = src[i];
        coldst[p] = d;
    }
}

// ---------------------------------------------------------------------------
// SGEMM with fused el/er epilogue.
// C[M,Nc] = A[M,K] @ B[K,Nc]; BM=128, BN=64, BK=16, 256 threads, 8x4 microtile.
// Block column bx == head (BN == D == 64). Epilogue computes
// el[r,head] = C_row . al[head], er likewise, via 16-lane shuffle reduce.
// ---------------------------------------------------------------------------
__global__ __launch_bounds__(256) void sgemm_fused_kernel(
    const float* __restrict__ A, const float* __restrict__ B, float* __restrict__ C,
    const float* __restrict__ al, const float* __restrict__ ar,
    float* __restrict__ el, float* __restrict__ er,
    int M, int K, int Nc, int H) {
    __shared__ float As[16][128];
    __shared__ float Bs[16][64];
    const unsigned FULL = 0xffffffffu;
    const int t = threadIdx.x;
    const int m0 = blockIdx.y * 128;
    const int n0 = blockIdx.x * 64;
    const int head = blockIdx.x;
    const int ty = t >> 4;
    const int tx = t & 15;
    const int arow = t >> 2;
    const int akc  = (t & 3) * 4;
    const int brow = t >> 4;
    const int bcol = (t & 15) * 4;

    float acc[8][4];
    #pragma unroll
    for (int i = 0; i < 8; i++)
        #pragma unroll
        for (int j = 0; j < 4; j++) acc[i][j] = 0.f;

    for (int k0 = 0; k0 < K; k0 += 16) {
        #pragma unroll
        for (int l = 0; l < 2; l++) {
            int r = arow + l * 64;
            float4 v = make_float4(0.f, 0.f, 0.f, 0.f);
            if (m0 + r < M)
                v = *(const float4*)&A[(size_t)(m0 + r) * K + k0 + akc];
            As[akc + 0][r] = v.x;
            As[akc + 1][r] = v.y;
            As[akc + 2][r] = v.z;
            As[akc + 3][r] = v.w;
        }
        float4 bv = *(const float4*)&B[(size_t)(k0 + brow) * Nc + n0 + bcol];
        *(float4*)&Bs[brow][bcol] = bv;
        __syncthreads();
        #pragma unroll
        for (int kk = 0; kk < 16; kk++) {
            float4 b4 = *(float4*)&Bs[kk][tx * 4];
            float4 a0 = *(float4*)&As[kk][ty * 8];
            float4 a1 = *(float4*)&As[kk][ty * 8 + 4];
            float av[8] = {a0.x, a0.y, a0.z, a0.w, a1.x, a1.y, a1.z, a1.w};
            #pragma unroll
            for (int i = 0; i < 8; i++) {
                acc[i][0] += av[i] * b4.x;
                acc[i][1] += av[i] * b4.y;
                acc[i][2] += av[i] * b4.z;
                acc[i][3] += av[i] * b4.w;
            }
        }
        __syncthreads();
    }
    #pragma unroll
    for (int i = 0; i < 8; i++) {
        int r = m0 + ty * 8 + i;
        if (r < M) {
            float4 o = make_float4(acc[i][0], acc[i][1], acc[i][2], acc[i][3]);
            *(float4*)&C[(size_t)r * Nc + n0 + tx * 4] = o;
        }
    }
    // --- fused el/er epilogue ---
    const float* alh = al + head * 64 + tx * 4;
    const float* arh = ar + head * 64 + tx * 4;
    float la0 = alh[0], la1 = alh[1], la2 = alh[2], la3 = alh[3];
    float ra0 = arh[0], ra1 = arh[1], ra2 = arh[2], ra3 = arh[3];
    #pragma unroll
    for (int i = 0; i < 8; i++) {
        float l = acc[i][0] * la0 + acc[i][1] * la1 + acc[i][2] * la2 + acc[i][3] * la3;
        float r = acc[i][0] * ra0 + acc[i][1] * ra1 + acc[i][2] * ra2 + acc[i][3] * ra3;
        #pragma unroll
        for (int o = 8; o; o >>= 1) {
            l += __shfl_xor_sync(FULL, l, o);
            r += __shfl_xor_sync(FULL, r, o);
        }
        int row = m0 + ty * 8 + i;
        if (tx == 0 && row < M) {
            el[(size_t)row * H + head] = l;
            er[(size_t)row * H + head] = r;
        }
    }
}

__device__ __forceinline__ float lrelu(float x) { return x > 0.f ? x : 0.2f * x; }

// ---------------------------------------------------------------------------
// Edge kernels: per CSR position, compute unnormalized softmax weights and
// accumulate per-(dst,head) sums with fp32 atomics.
// ---------------------------------------------------------------------------
__global__ void edge4_kernel(const int* __restrict__ colsrc, const int* __restrict__ coldst,
                             const float* __restrict__ el, const float* __restrict__ er,
                             float* __restrict__ ew, float* __restrict__ ssum, int E) {
    int p = blockIdx.x * blockDim.x + threadIdx.x;
    if (p >= E) return;
    int s = colsrc[p], d = coldst[p];
    float4 l = *(const float4*)&el[(size_t)s * 4];
    float4 r = *(const float4*)&er[(size_t)d * 4];
    float w0 = __expf(lrelu(l.x + r.x));
    float w1 = __expf(lrelu(l.y + r.y));
    float w2 = __expf(lrelu(l.z + r.z));
    float w3 = __expf(lrelu(l.w + r.w));
    *(float4*)&ew[(size_t)p * 4] = make_float4(w0, w1, w2, w3);
    atomicAdd(&ssum[(size_t)d * 4 + 0], w0);
    atomicAdd(&ssum[(size_t)d * 4 + 1], w1);
    atomicAdd(&ssum[(size_t)d * 4 + 2], w2);
    atomicAdd(&ssum[(size_t)d * 4 + 3], w3);
}

__global__ void edge1_kernel(const int* __restrict__ colsrc, const int* __restrict__ coldst,
                             const float* __restrict__ el, const float* __restrict__ er,
                             float* __restrict__ ew, float* __restrict__ ssum, int E) {
    int p = blockIdx.x * blockDim.x + threadIdx.x;
    if (p >= E) return;
    int s = colsrc[p], d = coldst[p];
    float w = __expf(lrelu(el[s] + er[d]));
    ew[p] = w;
    atomicAdd(&ssum[d], w);
}

// ---------------------------------------------------------------------------
// Aggregation, H=4 D=64: one warp per (node, 128-col half).
// ---------------------------------------------------------------------------
template <bool RELU>
__global__ __launch_bounds__(256) void agg4_kernel(
    const float* __restrict__ feat, const float* __restrict__ bias,
    const float* __restrict__ ssum, const int* __restrict__ rowptr,
    const int* __restrict__ colsrc, const float* __restrict__ ew,
    float* __restrict__ out, int N) {
    int gw = (blockIdx.x * blockDim.x + threadIdx.x) >> 5;
    if (gw >= 2 * N) return;
    const int n = gw >> 1;
    const int half = gw & 1;
    const int lane = threadIdx.x & 31;
    const int base = rowptr[n];
    const int deg = rowptr[n + 1] - base;
    const bool lo = (lane < 16);

    float4 s4 = *(const float4*)&ssum[(size_t)n * 4];
    float isA = 1.f / (half ? s4.z : s4.x);
    float isB = 1.f / (half ? s4.w : s4.y);
    const float is = lo ? isA : isB;
    const int c = half * 128 + lane * 4;

    float4 a = make_float4(0.f, 0.f, 0.f, 0.f);
    int i = 0;
    for (; i + 4 <= deg; i += 4) {
        int   sI[4];
        float wv[4];
        #pragma unroll
        for (int u = 0; u < 4; u++) {
            sI[u] = colsrc[base + i + u];
            float4 w4 = *(const float4*)&ew[(size_t)(base + i + u) * 4];
            float wA = half ? w4.z : w4.x;
            float wB = half ? w4.w : w4.y;
            wv[u] = (lo ? wA : wB) * is;
        }
        #pragma unroll
        for (int u = 0; u < 4; u++) {
            float4 f = *(const float4*)&feat[(size_t)sI[u] * 256 + c];
            a.x += f.x * wv[u]; a.y += f.y * wv[u];
            a.z += f.z * wv[u]; a.w += f.w * wv[u];
        }
    }
    for (; i < deg; i++) {
        int s = colsrc[base + i];
        float4 w4 = *(const float4*)&ew[(size_t)(base + i) * 4];
        float wA = half ? w4.z : w4.x;
        float wB = half ? w4.w : w4.y;
        float w = (lo ? wA : wB) * is;
        float4 f = *(const float4*)&feat[(size_t)s * 256 + c];
        a.x += f.x * w; a.y += f.y * w; a.z += f.z * w; a.w += f.w * w;
    }
    float4 b = *(const float4*)&bias[c];
    a.x += b.x; a.y += b.y; a.z += b.z; a.w += b.w;
    if (RELU) {
        a.x = fmaxf(a.x, 0.f); a.y = fmaxf(a.y, 0.f);
        a.z = fmaxf(a.z, 0.f); a.w = fmaxf(a.w, 0.f);
    }
    *(float4*)&out[(size_t)n * 256 + c] = a;
}

// ---------------------------------------------------------------------------
// Aggregation, H=1 D=64: one warp per node.
// ---------------------------------------------------------------------------
__global__ __launch_bounds__(256) void agg1_kernel(
    const float* __restrict__ feat, const float* __restrict__ bias,
    const float* __restrict__ ssum, const int* __restrict__ rowptr,
    const int* __restrict__ colsrc, const float* __restrict__ ew,
    float* __restrict__ out, int N) {
    int warp = (blockIdx.x * blockDim.x + threadIdx.x) >> 5;
    if (warp >= N) return;
    const int lane = threadIdx.x & 31;
    const int base = rowptr[warp];
    const int deg = rowptr[warp + 1] - base;
    const float is = 1.f / ssum[warp];
    const int c = lane * 2;
    float2 a = make_float2(0.f, 0.f);
    int i = 0;
    for (; i + 4 <= deg; i += 4) {
        int   sI[4];
        float wv[4];
        #pragma unroll
        for (int u = 0; u < 4; u++) {
            sI[u] = colsrc[base + i + u];
            wv[u] = ew[base + i + u] * is;
        }
        #pragma unroll
        for (int u = 0; u < 4; u++) {
            float2 f = *(const float2*)&feat[(size_t)sI[u] * 64 + c];
            a.x += f.x * wv[u];
            a.y += f.y * wv[u];
        }
    }
    for (; i < deg; i++) {
        int s = colsrc[base + i];
        float w = ew[base + i] * is;
        float2 f = *(const float2*)&feat[(size_t)s * 64 + c];
        a.x += f.x * w;
        a.y += f.y * w;
    }
    a.x += bias[c];
    a.y += bias[c + 1];
    *(float2*)&out[(size_t)warp * 64 + c] = a;
}

// ---------------------------------------------------------------------------
// kernel_launch
// ---------------------------------------------------------------------------
extern "C" void kernel_launch(void* const* d_in, const int* in_sizes, int n_in,
                              void* d_out, int out_size) {
    const float* features = (const float*)d_in[0];
    const int*   src      = (const int*)d_in[1];
    const int*   dst      = (const int*)d_in[2];
    const float* W1  = (const float*)d_in[3];
    const float* al1 = (const float*)d_in[4];
    const float* ar1 = (const float*)d_in[5];
    const float* b1  = (const float*)d_in[6];
    const float* W2  = (const float*)d_in[7];
    const float* al2 = (const float*)d_in[8];
    const float* ar2 = (const float*)d_in[9];
    const float* b2  = (const float*)d_in[10];
    const float* W3  = (const float*)d_in[11];
    const float* al3 = (const float*)d_in[12];
    const float* ar3 = (const float*)d_in[13];
    const float* b3  = (const float*)d_in[14];

    const int N = in_sizes[0] / 128;
    const int E = in_sizes[1];

    float *feat, *bufA, *bufB, *el, *er, *ew, *ssum;
    int *rowptr, *cursor, *cnt, *colsrc, *coldst;
    cudaGetSymbolAddress((void**)&feat,   g_feat);
    cudaGetSymbolAddress((void**)&bufA,   g_bufA);
    cudaGetSymbolAddress((void**)&bufB,   g_bufB);
    cudaGetSymbolAddress((void**)&el,     g_el);
    cudaGetSymbolAddress((void**)&er,     g_er);
    cudaGetSymbolAddress((void**)&ew,     g_ew);
    cudaGetSymbolAddress((void**)&ssum,   g_ssum);
    cudaGetSymbolAddress((void**)&rowptr, g_rowptr);
    cudaGetSymbolAddress((void**)&cursor, g_cursor);
    cudaGetSymbolAddress((void**)&cnt,    g_cnt);
    cudaGetSymbolAddress((void**)&colsrc, g_colsrc);
    cudaGetSymbolAddress((void**)&coldst, g_coldst);

    // --- CSR by dst ---
    cudaMemsetAsync(cnt, 0, (size_t)N * sizeof(int));
    hist_kernel<<<(E + 255) / 256, 256>>>(dst, cnt, E);
    scan_kernel<<<1, 1024>>>(cnt, rowptr, cursor, N, E);
    scatter_kernel<<<(E + 255) / 256, 256>>>(src, dst, cursor, colsrc, coldst, E);

    const int edgeGrid = (E + 255) / 256;
    const int aggGrid4 = (2 * N + 7) / 8;   // warp per (node, half)
    const int aggGrid1 = (N + 7) / 8;       // warp per node

    // --- Layer 1: IN=128 -> H*D=256 ---
    {
        dim3 grid(4, (N + 127) / 128);
        sgemm_fused_kernel<<<grid, 256>>>(features, W1, feat, al1, ar1, el, er, N, 128, 256, 4);
        cudaMemsetAsync(ssum, 0, (size_t)N * 4 * sizeof(float));
        edge4_kernel<<<edgeGrid, 256>>>(colsrc, coldst, el, er, ew, ssum, E);
        agg4_kernel<true><<<aggGrid4, 256>>>(feat, b1, ssum, rowptr, colsrc, ew, bufA, N);
    }
    // --- Layer 2: 256 -> 256 ---
    {
        dim3 grid(4, (N + 127) / 128);
        sgemm_fused_kernel<<<grid, 256>>>(bufA, W2, feat, al2, ar2, el, er, N, 256, 256, 4);
        cudaMemsetAsync(ssum, 0, (size_t)N * 4 * sizeof(float));
        edge4_kernel<<<edgeGrid, 256>>>(colsrc, coldst, el, er, ew, ssum, E);
        agg4_kernel<true><<<aggGrid4, 256>>>(feat, b2, ssum, rowptr, colsrc, ew, bufB, N);
    }
    // --- Layer 3: 256 -> 64 (H=1); mean over 1 head == identity ---
    {
        dim3 grid(1, (N + 127) / 128);
        sgemm_fused_kernel<<<grid, 256>>>(bufB, W3, feat, al3, ar3, el, er, N, 256, 64, 1);
        cudaMemsetAsync(ssum, 0, (size_t)N * sizeof(float));
        edge1_kernel<<<edgeGrid, 256>>>(colsrc, coldst, el, er, ew, ssum, E);
        agg1_kernel<<<aggGrid1, 256>>>(feat, b3, ssum, rowptr, colsrc, ew, (float*)d_out, N);
    }
}

// round 4
// speedup vs baseline: 1.1800x; 1.1800x over previous
#include <cuda_runtime.h>
#include <cuda_bf16.h>
#include <math.h>

// ---------------------------------------------------------------------------
// GAT 3-layer forward on GB300.
//   feat = H_in @ W  (+ fused el/er epilogue)   [double-buffered SGEMM, fp32]
//   agg (warp-per-dst-node, CSR):
//     pass A: ew = exp(lrelu(el[src]+er[dst])) stored; per-head sums (shuffle)
//     pass B: out = (1/s) * sum ew*feat[src] + b  (relu layers 1,2)
//   CSR build overlapped with layer-1 GEMM on a second stream.
// ---------------------------------------------------------------------------

#define MAXN 50000
#define MAXE 800000

__device__ float g_feat[MAXN * 256];
__device__ float g_bufA[MAXN * 256];
__device__ float g_bufB[MAXN * 256];
__device__ float g_el[MAXN * 4];
__device__ float g_er[MAXN * 4];
__device__ float g_ew[MAXE * 4];
__device__ int   g_rowptr[MAXN + 1];
__device__ int   g_cursor[MAXN];
__device__ int   g_cnt[MAXN];
__device__ int   g_colsrc[MAXE];

// ---------------------------------------------------------------------------
// CSR build
// ---------------------------------------------------------------------------
__global__ void hist_kernel(const int* __restrict__ dst, int* __restrict__ cnt, int E) {
    int i = blockIdx.x * blockDim.x + threadIdx.x;
    if (i < E) atomicAdd(&cnt[dst[i]], 1);
}

__global__ void scan_kernel(const int* __restrict__ cnt, int* __restrict__ rowptr,
                            int* __restrict__ cursor, int N, int E) {
    __shared__ int sums[1024];
    int tid = threadIdx.x;
    int chunk = (N + 1023) >> 10;
    int start = tid * chunk;
    int end = min(start + chunk, N);
    int s = 0;
    for (int i = start; i < end; i++) s += cnt[i];
    sums[tid] = s;
    __syncthreads();
    for (int off = 1; off < 1024; off <<= 1) {
        int v = (tid >= off) ? sums[tid - off] : 0;
        __syncthreads();
        sums[tid] += v;
        __syncthreads();
    }
    int run = sums[tid] - s;
    for (int i = start; i < end; i++) {
        rowptr[i] = run;
        cursor[i] = run;
        run += cnt[i];
    }
    if (tid == 0) rowptr[N] = E;
}

__global__ void scatter_kernel(const int* __restrict__ src, const int* __restrict__ dst,
                               int* __restrict__ cursor, int* __restrict__ colsrc, int E) {
    int i = blockIdx.x * blockDim.x + threadIdx.x;
    if (i < E) {
        int p = atomicAdd(&cursor[dst[i]], 1);
        colsrc[p] = src[i];
    }
}

// ---------------------------------------------------------------------------
// Double-buffered SGEMM with fused el/er epilogue.
// C[M,Nc] = A[M,K] @ B[K,Nc]; BM=128, BN=64, BK=16, 256 threads, 8x4 microtile.
// Block column bx == head (BN == D == 64).
// ---------------------------------------------------------------------------
__global__ __launch_bounds__(256) void sgemm_fused_kernel(
    const float* __restrict__ A, const float* __restrict__ B, float* __restrict__ C,
    const float* __restrict__ al, const float* __restrict__ ar,
    float* __restrict__ el, float* __restrict__ er,
    int M, int K, int Nc, int H) {
    __shared__ float As[2][16][128];
    __shared__ float Bs[2][16][64];
    const unsigned FULL = 0xffffffffu;
    const int t = threadIdx.x;
    const int m0 = blockIdx.y * 128;
    const int n0 = blockIdx.x * 64;
    const int head = blockIdx.x;
    const int ty = t >> 4;
    const int tx = t & 15;
    const int arow = t >> 2;        // 0..63
    const int akc  = (t & 3) * 4;   // 0,4,8,12
    const int brow = t >> 4;        // 0..15
    const int bcol = (t & 15) * 4;  // 0..60

    const bool aval0 = (m0 + arow) < M;
    const bool aval1 = (m0 + arow + 64) < M;
    const float* Ap0 = A + (size_t)(m0 + arow) * K + akc;
    const float* Ap1 = A + (size_t)(m0 + arow + 64) * K + akc;
    const float* Bp  = B + (size_t)brow * Nc + n0 + bcol;

    float acc[8][4];
    #pragma unroll
    for (int i = 0; i < 8; i++)
        #pragma unroll
        for (int j = 0; j < 4; j++) acc[i][j] = 0.f;

    // prologue: tile 0 -> buffer 0
    {
        float4 v0 = aval0 ? *(const float4*)Ap0 : make_float4(0.f, 0.f, 0.f, 0.f);
        float4 v1 = aval1 ? *(const float4*)Ap1 : make_float4(0.f, 0.f, 0.f, 0.f);
        float4 bv = *(const float4*)Bp;
        As[0][akc + 0][arow] = v0.x; As[0][akc + 1][arow] = v0.y;
        As[0][akc + 2][arow] = v0.z; As[0][akc + 3][arow] = v0.w;
        As[0][akc + 0][arow + 64] = v1.x; As[0][akc + 1][arow + 64] = v1.y;
        As[0][akc + 2][arow + 64] = v1.z; As[0][akc + 3][arow + 64] = v1.w;
        *(float4*)&Bs[0][brow][bcol] = bv;
    }
    __syncthreads();

    int buf = 0;
    for (int k0 = 16; k0 < K; k0 += 16) {
        float4 v0 = aval0 ? *(const float4*)(Ap0 + k0) : make_float4(0.f, 0.f, 0.f, 0.f);
        float4 v1 = aval1 ? *(const float4*)(Ap1 + k0) : make_float4(0.f, 0.f, 0.f, 0.f);
        float4 bv = *(const float4*)(Bp + (size_t)k0 * Nc);
        #pragma unroll
        for (int kk = 0; kk < 16; kk++) {
            float4 b4 = *(float4*)&Bs[buf][kk][tx * 4];
            float4 a0 = *(float4*)&As[buf][kk][ty * 8];
            float4 a1 = *(float4*)&As[buf][kk][ty * 8 + 4];
            float av[8] = {a0.x, a0.y, a0.z, a0.w, a1.x, a1.y, a1.z, a1.w};
            #pragma unroll
            for (int i = 0; i < 8; i++) {
                acc[i][0] += av[i] * b4.x;
                acc[i][1] += av[i] * b4.y;
                acc[i][2] += av[i] * b4.z;
                acc[i][3] += av[i] * b4.w;
            }
        }
        int nb = buf ^ 1;
        As[nb][akc + 0][arow] = v0.x; As[nb][akc + 1][arow] = v0.y;
        As[nb][akc + 2][arow] = v0.z; As[nb][akc + 3][arow] = v0.w;
        As[nb][akc + 0][arow + 64] = v1.x; As[nb][akc + 1][arow + 64] = v1.y;
        As[nb][akc + 2][arow + 64] = v1.z; As[nb][akc + 3][arow + 64] = v1.w;
        *(float4*)&Bs[nb][brow][bcol] = bv;
        __syncthreads();
        buf = nb;
    }
    // final tile
    #pragma unroll
    for (int kk = 0; kk < 16; kk++) {
        float4 b4 = *(float4*)&Bs[buf][kk][tx * 4];
        float4 a0 = *(float4*)&As[buf][kk][ty * 8];
        float4 a1 = *(float4*)&As[buf][kk][ty * 8 + 4];
        float av[8] = {a0.x, a0.y, a0.z, a0.w, a1.x, a1.y, a1.z, a1.w};
        #pragma unroll
        for (int i = 0; i < 8; i++) {
            acc[i][0] += av[i] * b4.x;
            acc[i][1] += av[i] * b4.y;
            acc[i][2] += av[i] * b4.z;
            acc[i][3] += av[i] * b4.w;
        }
    }

    #pragma unroll
    for (int i = 0; i < 8; i++) {
        int r = m0 + ty * 8 + i;
        if (r < M) {
            float4 o = make_float4(acc[i][0], acc[i][1], acc[i][2], acc[i][3]);
            *(float4*)&C[(size_t)r * Nc + n0 + tx * 4] = o;
        }
    }
    // --- fused el/er epilogue ---
    const float* alh = al + head * 64 + tx * 4;
    const float* arh = ar + head * 64 + tx * 4;
    float la0 = alh[0], la1 = alh[1], la2 = alh[2], la3 = alh[3];
    float ra0 = arh[0], ra1 = arh[1], ra2 = arh[2], ra3 = arh[3];
    #pragma unroll
    for (int i = 0; i < 8; i++) {
        float l = acc[i][0] * la0 + acc[i][1] * la1 + acc[i][2] * la2 + acc[i][3] * la3;
        float r = acc[i][0] * ra0 + acc[i][1] * ra1 + acc[i][2] * ra2 + acc[i][3] * ra3;
        #pragma unroll
        for (int o = 8; o; o >>= 1) {
            l += __shfl_xor_sync(FULL, l, o);
            r += __shfl_xor_sync(FULL, r, o);
        }
        int row = m0 + ty * 8 + i;
        if (tx == 0 && row < M) {
            el[(size_t)row * H + head] = l;
            er[(size_t)row * H + head] = r;
        }
    }
}

__device__ __forceinline__ float lrelu(float x) { return x > 0.f ? x : 0.2f * x; }

// ---------------------------------------------------------------------------
// Aggregation H=4, D=64: one warp per dst node. No max-shift (safe: |logit|<~8).
// ---------------------------------------------------------------------------
template <bool RELU>
__global__ __launch_bounds__(256) void agg4_kernel(
    const float* __restrict__ feat, const float* __restrict__ el,
    const float* __restrict__ er, const float* __restrict__ bias,
    const int* __restrict__ rowptr, const int* __restrict__ colsrc,
    float* __restrict__ ew, float* __restrict__ out, int N) {
    const unsigned FULL = 0xffffffffu;
    int n = (blockIdx.x * blockDim.x + threadIdx.x) >> 5;
    int lane = threadIdx.x & 31;
    if (n >= N) return;
    const int base = rowptr[n];
    const int deg = rowptr[n + 1] - base;

    float4 r4 = *(const float4*)&er[(size_t)n * 4];
    float s0 = 0.f, s1 = 0.f, s2 = 0.f, s3 = 0.f;

    // Pass A: compute unnormalized weights, store, accumulate sums
    for (int i0 = 0; i0 < deg; i0 += 32) {
        int i = i0 + lane;
        bool act = i < deg;
        int s = colsrc[base + (act ? i : 0)];
        float4 l4 = *(const float4*)&el[(size_t)s * 4];
        float w0 = __expf(lrelu(l4.x + r4.x));
        float w1 = __expf(lrelu(l4.y + r4.y));
        float w2 = __expf(lrelu(l4.z + r4.z));
        float w3 = __expf(lrelu(l4.w + r4.w));
        if (act) {
            *(float4*)&ew[(size_t)(base + i) * 4] = make_float4(w0, w1, w2, w3);
            s0 += w0; s1 += w1; s2 += w2; s3 += w3;
        }
    }
    #pragma unroll
    for (int o = 16; o; o >>= 1) {
        s0 += __shfl_xor_sync(FULL, s0, o);
        s1 += __shfl_xor_sync(FULL, s1, o);
        s2 += __shfl_xor_sync(FULL, s2, o);
        s3 += __shfl_xor_sync(FULL, s3, o);
    }
    const bool lo = (lane < 16);
    const float isA = 1.f / (lo ? s0 : s1);   // cols 0..127: heads 0,1
    const float isB = 1.f / (lo ? s2 : s3);   // cols 128..255: heads 2,3
    const int c0 = lane * 4, c1 = 128 + lane * 4;

    // Pass B: weighted gather-accumulate, unroll 8
    float4 a0 = make_float4(0.f, 0.f, 0.f, 0.f);
    float4 a1 = make_float4(0.f, 0.f, 0.f, 0.f);
    int i = 0;
    for (; i + 8 <= deg; i += 8) {
        int   sI[8];
        float wa[8], wb[8];
        #pragma unroll
        for (int u = 0; u < 8; u++) {
            sI[u] = colsrc[base + i + u];
            float4 w4 = *(const float4*)&ew[(size_t)(base + i + u) * 4];
            wa[u] = (lo ? w4.x : w4.y) * isA;
            wb[u] = (lo ? w4.z : w4.w) * isB;
        }
        #pragma unroll
        for (int u = 0; u < 8; u++) {
            const float* fs = feat + (size_t)sI[u] * 256;
            float4 f0 = *(const float4*)&fs[c0];
            float4 f1 = *(const float4*)&fs[c1];
            a0.x += f0.x * wa[u]; a0.y += f0.y * wa[u];
            a0.z += f0.z * wa[u]; a0.w += f0.w * wa[u];
            a1.x += f1.x * wb[u]; a1.y += f1.y * wb[u];
            a1.z += f1.z * wb[u]; a1.w += f1.w * wb[u];
        }
    }
    for (; i < deg; i++) {
        int s = colsrc[base + i];
        float4 w4 = *(const float4*)&ew[(size_t)(base + i) * 4];
        float wA = (lo ? w4.x : w4.y) * isA;
        float wB = (lo ? w4.z : w4.w) * isB;
        const float* fs = feat + (size_t)s * 256;
        float4 f0 = *(const float4*)&fs[c0];
        float4 f1 = *(const float4*)&fs[c1];
        a0.x += f0.x * wA; a0.y += f0.y * wA; a0.z += f0.z * wA; a0.w += f0.w * wA;
        a1.x += f1.x * wB; a1.y += f1.y * wB; a1.z += f1.z * wB; a1.w += f1.w * wB;
    }
    float4 b0 = *(const float4*)&bias[c0];
    float4 b1 = *(const float4*)&bias[c1];
    a0.x += b0.x; a0.y += b0.y; a0.z += b0.z; a0.w += b0.w;
    a1.x += b1.x; a1.y += b1.y; a1.z += b1.z; a1.w += b1.w;
    if (RELU) {
        a0.x = fmaxf(a0.x, 0.f); a0.y = fmaxf(a0.y, 0.f);
        a0.z = fmaxf(a0.z, 0.f); a0.w = fmaxf(a0.w, 0.f);
        a1.x = fmaxf(a1.x, 0.f); a1.y = fmaxf(a1.y, 0.f);
        a1.z = fmaxf(a1.z, 0.f); a1.w = fmaxf(a1.w, 0.f);
    }
    *(float4*)&out[(size_t)n * 256 + c0] = a0;
    *(float4*)&out[(size_t)n * 256 + c1] = a1;
}

// ---------------------------------------------------------------------------
// Aggregation H=1, D=64: one warp per dst node.
// ---------------------------------------------------------------------------
__global__ __launch_bounds__(256) void agg1_kernel(
    const float* __restrict__ feat, const float* __restrict__ el,
    const float* __restrict__ er, const float* __restrict__ bias,
    const int* __restrict__ rowptr, const int* __restrict__ colsrc,
    float* __restrict__ ew, float* __restrict__ out, int N) {
    const unsigned FULL = 0xffffffffu;
    int n = (blockIdx.x * blockDim.x + threadIdx.x) >> 5;
    int lane = threadIdx.x & 31;
    if (n >= N) return;
    const int base = rowptr[n];
    const int deg = rowptr[n + 1] - base;
    const float rn = er[n];

    float s0 = 0.f;
    for (int i0 = 0; i0 < deg; i0 += 32) {
        int i = i0 + lane;
        bool act = i < deg;
        int s = colsrc[base + (act ? i : 0)];
        float w = __expf(lrelu(el[s] + rn));
        if (act) { ew[base + i] = w; s0 += w; }
    }
    #pragma unroll
    for (int o = 16; o; o >>= 1) s0 += __shfl_xor_sync(FULL, s0, o);
    const float is = 1.f / s0;
    const int c = lane * 2;

    float2 a = make_float2(0.f, 0.f);
    int i = 0;
    for (; i + 8 <= deg; i += 8) {
        int   sI[8];
        float wv[8];
        #pragma unroll
        for (int u = 0; u < 8; u++) {
            sI[u] = colsrc[base + i + u];
            wv[u] = ew[base + i + u] * is;
        }
        #pragma unroll
        for (int u = 0; u < 8; u++) {
            float2 f = *(const float2*)&feat[(size_t)sI[u] * 64 + c];
            a.x += f.x * wv[u];
            a.y += f.y * wv[u];
        }
    }
    for (; i < deg; i++) {
        int s = colsrc[base + i];
        float w = ew[base + i] * is;
        float2 f = *(const float2*)&feat[(size_t)s * 64 + c];
        a.x += f.x * w;
        a.y += f.y * w;
    }
    a.x += bias[c];
    a.y += bias[c + 1];
    *(float2*)&out[(size_t)n * 64 + c] = a;
}

// ---------------------------------------------------------------------------
// kernel_launch
// ---------------------------------------------------------------------------
extern "C" void kernel_launch(void* const* d_in, const int* in_sizes, int n_in,
                              void* d_out, int out_size) {
    const float* features = (const float*)d_in[0];
    const int*   src      = (const int*)d_in[1];
    const int*   dst      = (const int*)d_in[2];
    const float* W1  = (const float*)d_in[3];
    const float* al1 = (const float*)d_in[4];
    const float* ar1 = (const float*)d_in[5];
    const float* b1  = (const float*)d_in[6];
    const float* W2  = (const float*)d_in[7];
    const float* al2 = (const float*)d_in[8];
    const float* ar2 = (const float*)d_in[9];
    const float* b2  = (const float*)d_in[10];
    const float* W3  = (const float*)d_in[11];
    const float* al3 = (const float*)d_in[12];
    const float* ar3 = (const float*)d_in[13];
    const float* b3  = (const float*)d_in[14];

    const int N = in_sizes[0] / 128;
    const int E = in_sizes[1];

    float *feat, *bufA, *bufB, *el, *er, *ew;
    int *rowptr, *cursor, *cnt, *colsrc;
    cudaGetSymbolAddress((void**)&feat,   g_feat);
    cudaGetSymbolAddress((void**)&bufA,   g_bufA);
    cudaGetSymbolAddress((void**)&bufB,   g_bufB);
    cudaGetSymbolAddress((void**)&el,     g_el);
    cudaGetSymbolAddress((void**)&er,     g_er);
    cudaGetSymbolAddress((void**)&ew,     g_ew);
    cudaGetSymbolAddress((void**)&rowptr, g_rowptr);
    cudaGetSymbolAddress((void**)&cursor, g_cursor);
    cudaGetSymbolAddress((void**)&cnt,    g_cnt);
    cudaGetSymbolAddress((void**)&colsrc, g_colsrc);

    // Lazily created aux stream + events (created once, outside capture).
    static cudaStream_t s_aux = nullptr;
    static cudaEvent_t e_fork = nullptr, e_join = nullptr;
    if (s_aux == nullptr) {
        cudaStreamCreateWithFlags(&s_aux, cudaStreamNonBlocking);
        cudaEventCreateWithFlags(&e_fork, cudaEventDisableTiming);
        cudaEventCreateWithFlags(&e_join, cudaEventDisableTiming);
    }

    // --- CSR build on aux stream, overlapped with layer-1 GEMM ---
    cudaEventRecord(e_fork, 0);
    cudaStreamWaitEvent(s_aux, e_fork, 0);
    cudaMemsetAsync(cnt, 0, (size_t)N * sizeof(int), s_aux);
    hist_kernel<<<(E + 255) / 256, 256, 0, s_aux>>>(dst, cnt, E);
    scan_kernel<<<1, 1024, 0, s_aux>>>(cnt, rowptr, cursor, N, E);
    scatter_kernel<<<(E + 255) / 256, 256, 0, s_aux>>>(src, dst, cursor, colsrc, E);
    cudaEventRecord(e_join, s_aux);

    const int aggGrid = (N + 7) / 8;  // 8 warps per block

    // --- Layer 1: IN=128 -> H*D=256 ---
    {
        dim3 grid(4, (N + 127) / 128);
        sgemm_fused_kernel<<<grid, 256>>>(features, W1, feat, al1, ar1, el, er, N, 128, 256, 4);
        cudaStreamWaitEvent(0, e_join, 0);  // CSR ready
        agg4_kernel<true><<<aggGrid, 256>>>(feat, el, er, b1, rowptr, colsrc, ew, bufA, N);
    }
    // --- Layer 2: 256 -> 256 ---
    {
        dim3 grid(4, (N + 127) / 128);
        sgemm_fused_kernel<<<grid, 256>>>(bufA, W2, feat, al2, ar2, el, er, N, 256, 256, 4);
        agg4_kernel<true><<<aggGrid, 256>>>(feat, el, er, b2, rowptr, colsrc, ew, bufB, N);
    }
    // --- Layer 3: 256 -> 64 (H=1); mean over 1 head == identity ---
    {
        dim3 grid(1, (N + 127) / 128);
        sgemm_fused_kernel<<<grid, 256>>>(bufB, W3, feat, al3, ar3, el, er, N, 256, 64, 1);
        agg1_kernel<<<aggGrid, 256>>>(feat, el, er, b3, rowptr, colsrc, ew, (float*)d_out, N);
    }
}